// round 4
// baseline (speedup 1.0000x reference)
#include <cuda_runtime.h>

#define BB 64
#define NN 2048
#define MM 256
#define MSPLIT 8                   // pass-3 blocks per batch (32 floats of M each)

// ---- scratch (static __device__ globals; no allocation) ----
__device__ float2 g_dots[BB * NN];   // (dot, sumsq) per memory row   1 MB

// ============================================================================
// Pass 1: per-row dot(mem_row, k) and sum-of-squares. Warp per row.
// grid = B*N/8 = 16384 blocks, block = 256 (8 warps). Streams 134 MB once.
// ============================================================================
__global__ void k_pass1(const float* __restrict__ mem, const float* __restrict__ k)
{
    __shared__ float4 sk[MM / 4];
    const int bidx = blockIdx.x;          // 256 blocks per batch
    const int b = bidx >> 8;
    const int t = threadIdx.x;
    if (t < MM / 4) sk[t] = reinterpret_cast<const float4*>(k + (size_t)b * MM)[t];
    __syncthreads();

    const int warp = t >> 5, lane = t & 31;
    const size_t row = (size_t)bidx * 8 + warp;
    const float4* mr = reinterpret_cast<const float4*>(mem + row * MM);

    float4 v0 = mr[lane];
    float4 v1 = mr[lane + 32];
    float4 k0 = sk[lane];
    float4 k1 = sk[lane + 32];

    float dot = v0.x * k0.x + v0.y * k0.y + v0.z * k0.z + v0.w * k0.w
              + v1.x * k1.x + v1.y * k1.y + v1.z * k1.z + v1.w * k1.w;
    float ss  = v0.x * v0.x + v0.y * v0.y + v0.z * v0.z + v0.w * v0.w
              + v1.x * v1.x + v1.y * v1.y + v1.z * v1.z + v1.w * v1.w;

    #pragma unroll
    for (int off = 16; off > 0; off >>= 1) {
        dot += __shfl_down_sync(0xffffffffu, dot, off);
        ss  += __shfl_down_sync(0xffffffffu, ss,  off);
    }
    if (lane == 0) g_dots[row] = make_float2(dot, ss);
}

// ============================================================================
// Block-wide reduction over 256 threads (sum or max), broadcast to all.
// ============================================================================
template <bool IS_MAX>
__device__ __forceinline__ float block_reduce256(float v)
{
    __shared__ float sh[8];
    const int lane = threadIdx.x & 31, warp = threadIdx.x >> 5;
    #pragma unroll
    for (int off = 16; off > 0; off >>= 1) {
        float o = __shfl_down_sync(0xffffffffu, v, off);
        v = IS_MAX ? fmaxf(v, o) : (v + o);
    }
    if (lane == 0) sh[warp] = v;
    __syncthreads();
    if (threadIdx.x == 0) {
        float r = sh[0];
        #pragma unroll
        for (int i = 1; i < 8; i++) r = IS_MAX ? fmaxf(r, sh[i]) : (r + sh[i]);
        sh[0] = r;
    }
    __syncthreads();
    float r = sh[0];
    __syncthreads();
    return r;
}

// ============================================================================
// Pass 3 (fused): softmax prologue + final GEMV + output.
// grid = BB * MSPLIT = 512 blocks (single resident wave), block = 256.
// Block (b, ms) owns output columns [ms*32, ms*32+32) of batch b.
//   Prologue: recompute w_r from g_dots (redundant across the 8 blocks of a
//             batch; inputs tiny + L2-resident), build c[n] in smem and the
//             scalar s = sum w_r*w_w.
//   Main:     acc[m] = sum_n c[n] * mem[b,n,m] over N=2048 rows; the re-read
//             is mostly L2-resident from pass 1 (134MB tensor vs ~120MB+ L2).
//   Epilogue: out = acc + s * k.   No partials, no extra kernel.
// ============================================================================
__global__ void k_pass3(const float* __restrict__ mem, const float* __restrict__ k,
                        const float* __restrict__ g,   const float* __restrict__ w_prev,
                        const int* __restrict__ w_lu_prev, float* __restrict__ out)
{
    const int b  = BB - 1 - ((int)blockIdx.x >> 3);   // descending batches
    const int ms = (int)blockIdx.x & 7;
    const int t  = threadIdx.x;

    __shared__ float  sc[NN];                       // c[n]              8 KB
    __shared__ float  sk[MM];                       // k[b,:]            1 KB
    __shared__ float4 red[8][MM / 4 / MSPLIT];      // epilogue reduce   1 KB
    __shared__ float  s_sh;

    // ---- prologue: k norm ----
    float kv = k[(size_t)b * MM + t];
    sk[t] = kv;
    float ksum = block_reduce256<false>(kv * kv);
    float knrm = fmaxf(sqrtf(ksum), 1e-8f);

    // ---- cosine + max ----
    const float2* dots_b = g_dots + (size_t)b * NN;
    float cosv[8];
    float mx = -1e30f;
    #pragma unroll
    for (int i = 0; i < 8; i++) {
        float2 d = dots_b[t + i * 256];
        float nrm = fmaxf(sqrtf(d.y), 1e-8f);
        float cv = d.x / (nrm * knrm);
        cosv[i] = cv;
        mx = fmaxf(mx, cv);
    }
    float gmx = block_reduce256<true>(mx);

    // ---- softmax denom ----
    float ex[8];
    float lsum = 0.f;
    #pragma unroll
    for (int i = 0; i < 8; i++) { ex[i] = __expf(cosv[i] - gmx); lsum += ex[i]; }
    float S = block_reduce256<false>(lsum);
    float inv = 1.f / S;

    // ---- c[n] into smem, s scalar ----
    const float gb = g[b];
    float sacc = 0.f;
    #pragma unroll
    for (int i = 0; i < 8; i++) {
        int n = t + i * 256;
        float wr  = ex[i] * inv;
        float wrp = w_prev[((size_t)b * 2 + 1) * NN + n];   // w_prev[:,1,:]
        float wlu = (float)w_lu_prev[(size_t)b * NN + n];
        float ww  = gb * wrp + (1.f - gb) * wlu;
        sc[n] = wr * (1.f - wlu);
        sacc += wr * ww;
    }
    float stot = block_reduce256<false>(sacc);
    if (t == 0) s_sh = stot;
    __syncthreads();

    // ---- main GEMV over all N rows ----
    // 256 threads = 32 row-subgroups x 8 float4-columns; unroll 8 for MLP.
    const int q   = t & 7;        // float4 column within the 32-float slice
    const int sub = t >> 3;       // 0..31 : row subgroup
    const float4* base = reinterpret_cast<const float4*>(mem)
                       + (size_t)b * NN * (MM / 4) + ms * 8;

    float4 acc = make_float4(0.f, 0.f, 0.f, 0.f);
    #pragma unroll 8
    for (int it = 0; it < NN / 32; it++) {
        int r = it * 32 + sub;
        float  c = sc[r];
        float4 v = base[(size_t)r * (MM / 4) + q];
        acc.x += c * v.x; acc.y += c * v.y; acc.z += c * v.z; acc.w += c * v.w;
    }

    // ---- epilogue reduce: 32 subgroups -> 1 ----
    // Stage 1: warp-internal shuffle. Lanes l, l+8, l+16, l+24 share q; the two
    //          shuffles sum them into lanes 0..7 of each warp.
    #pragma unroll
    for (int off = 16; off >= 8; off >>= 1) {
        acc.x += __shfl_down_sync(0xffffffffu, acc.x, off);
        acc.y += __shfl_down_sync(0xffffffffu, acc.y, off);
        acc.z += __shfl_down_sync(0xffffffffu, acc.z, off);
        acc.w += __shfl_down_sync(0xffffffffu, acc.w, off);
    }
    if ((t & 31) < 8) red[t >> 5][t & 7] = acc;
    __syncthreads();
    // Stage 2: 8 warps' partials summed by the first 8 threads + epilogue.
    if (t < 8) {
        float4 a = red[0][t];
        #pragma unroll
        for (int w = 1; w < 8; w++) {
            float4 o = red[w][t];
            a.x += o.x; a.y += o.y; a.z += o.z; a.w += o.w;
        }
        float s = s_sh;
        int m0 = ms * 32 + t * 4;
        float* o = out + (size_t)b * MM + m0;
        o[0] = a.x + s * sk[m0 + 0];
        o[1] = a.y + s * sk[m0 + 1];
        o[2] = a.z + s * sk[m0 + 2];
        o[3] = a.w + s * sk[m0 + 3];
    }
}

// ============================================================================
extern "C" void kernel_launch(void* const* d_in, const int* in_sizes, int n_in,
                              void* d_out, int out_size)
{
    const float* mem       = (const float*)d_in[0];   // (64,2048,256) f32
    const float* k         = (const float*)d_in[1];   // (64,256) f32
    const float* g         = (const float*)d_in[2];   // (64,1) f32
    // d_in[3] gamma: unused (dead w.r.t. output)
    const float* w_prev    = (const float*)d_in[4];   // (64,2,2048) f32
    const int*   w_lu_prev = (const int*)d_in[5];     // (64,2048) i32
    // d_in[6] n: unused (sort/w_lu are dead w.r.t. output)
    float* out = (float*)d_out;                       // (64,256) f32

    k_pass1<<<(BB * NN) / 8, 256>>>(mem, k);
    k_pass3<<<BB * MSPLIT, 256>>>(mem, k, g, w_prev, w_lu_prev, out);
}

// round 6
// speedup vs baseline: 1.5000x; 1.5000x over previous
#include <cuda_runtime.h>

#define BB 64
#define NN 2048
#define MM 256
#define CHUNKS 32                        // partial chunks per batch
#define ROWS_PER_BLOCK (NN / CHUNKS)     // 64 rows per pass-A block

// ---- scratch (static __device__ globals; no allocation) ----
__device__ float  g_partial[CHUNKS * BB * MM];   // chunk-major partial vectors, 2 MB
__device__ float2 g_scal[CHUNKS * BB];           // (sum u, sum u*ww) per chunk

// ============================================================================
// Pass A: SINGLE streaming pass over memory (134 MB read once).
// Block (b, chunk) handles 64 rows. Per row (warp-cooperative):
//   dot = <row, k>, ss = <row, row>  via butterfly shuffle (all lanes get it)
//   u = exp( dot / (||row|| * ||k||) )      [cos in [-1,1] -> no max needed]
//   acc += u * (1 - wlu_prev[n]) * row      [row still in registers!]
//   U += u ;  W += u * ww[n]
// Block epilogue: reduce 8 warps' 256-float accumulators -> g_partial,
// reduce scalars -> g_scal.
// grid = BB*CHUNKS = 2048 blocks, block = 256 (8 warps x 8 rows each).
// ============================================================================
__global__ void k_passA(const float* __restrict__ mem, const float* __restrict__ k,
                        const float* __restrict__ g,   const float* __restrict__ w_prev,
                        const int* __restrict__ w_lu_prev)
{
    const int bid   = blockIdx.x;
    const int b     = bid >> 5;          // / CHUNKS
    const int chunk = bid & (CHUNKS - 1);
    const int row0  = chunk * ROWS_PER_BLOCK;
    const int t     = threadIdx.x;
    const int warp  = t >> 5, lane = t & 31;

    __shared__ float4 sk4[MM / 4];           // k[b,:]
    __shared__ float  s_mask[ROWS_PER_BLOCK];
    __shared__ float  s_ww[ROWS_PER_BLOCK];
    __shared__ float  s_red[8];              // knorm reduce
    __shared__ float  s_kinv;

    // ---- k into smem + ||k|| ----
    if (t < MM / 4) sk4[t] = reinterpret_cast<const float4*>(k + (size_t)b * MM)[t];
    float kv = k[(size_t)b * MM + t];
    float ks = kv * kv;
    #pragma unroll
    for (int off = 16; off > 0; off >>= 1) ks += __shfl_down_sync(0xffffffffu, ks, off);
    if (lane == 0) s_red[warp] = ks;

    // ---- per-row mask and ww coefficients ----
    const float gb = g[b];
    if (t < ROWS_PER_BLOCK) {
        int n = row0 + t;
        float wlu = (float)w_lu_prev[(size_t)b * NN + n];
        float wrp = w_prev[((size_t)b * 2 + 1) * NN + n];    // w_prev[:,1,:]
        s_mask[t] = 1.f - wlu;
        s_ww[t]   = gb * wrp + (1.f - gb) * wlu;
    }
    __syncthreads();
    if (t == 0) {
        float r = s_red[0];
        #pragma unroll
        for (int i = 1; i < 8; i++) r += s_red[i];
        s_kinv = 1.f / fmaxf(sqrtf(r), 1e-8f);
    }
    __syncthreads();

    const float  kinv = s_kinv;
    const float4 k0 = sk4[lane], k1 = sk4[lane + 32];
    const float4* base = reinterpret_cast<const float4*>(
        mem + ((size_t)b * NN + row0) * MM);

    float4 acc0 = make_float4(0.f, 0.f, 0.f, 0.f);
    float4 acc1 = make_float4(0.f, 0.f, 0.f, 0.f);
    float  U = 0.f, W = 0.f;

    #pragma unroll
    for (int r8 = 0; r8 < 8; r8++) {
        const int rl = warp * 8 + r8;                 // local row 0..63
        float4 v0 = base[(size_t)rl * (MM / 4) + lane];
        float4 v1 = base[(size_t)rl * (MM / 4) + lane + 32];

        float dot = v0.x * k0.x + v0.y * k0.y + v0.z * k0.z + v0.w * k0.w
                  + v1.x * k1.x + v1.y * k1.y + v1.z * k1.z + v1.w * k1.w;
        float ss  = v0.x * v0.x + v0.y * v0.y + v0.z * v0.z + v0.w * v0.w
                  + v1.x * v1.x + v1.y * v1.y + v1.z * v1.z + v1.w * v1.w;
        #pragma unroll
        for (int off = 16; off > 0; off >>= 1) {
            dot += __shfl_xor_sync(0xffffffffu, dot, off);
            ss  += __shfl_xor_sync(0xffffffffu, ss,  off);
        }
        // ||row|| >= 1e-8 guard folded into rsqrt argument
        float u = __expf(dot * kinv * rsqrtf(fmaxf(ss, 1e-16f)));
        float c = u * s_mask[rl];
        acc0.x += c * v0.x; acc0.y += c * v0.y; acc0.z += c * v0.z; acc0.w += c * v0.w;
        acc1.x += c * v1.x; acc1.y += c * v1.y; acc1.z += c * v1.z; acc1.w += c * v1.w;
        if (lane == 0) { U += u; W += u * s_ww[rl]; }
    }

    // ---- block epilogue: reduce 8 warp accumulators -> one 256-vector ----
    __shared__ float4 red0[8][32];
    __shared__ float4 red1[8][32];
    __shared__ float  sU[8], sW[8];
    red0[warp][lane] = acc0;
    red1[warp][lane] = acc1;
    if (lane == 0) { sU[warp] = U; sW[warp] = W; }
    __syncthreads();

    if (t < 64) {
        float4 s = make_float4(0.f, 0.f, 0.f, 0.f);
        #pragma unroll
        for (int w = 0; w < 8; w++) {
            float4 a = (t < 32) ? red0[w][t] : red1[w][t - 32];
            s.x += a.x; s.y += a.y; s.z += a.z; s.w += a.w;
        }
        reinterpret_cast<float4*>(
            g_partial + ((size_t)chunk * BB + b) * MM)[t] = s;
    }
    if (t == 0) {
        float Ut = sU[0], Wt = sW[0];
        #pragma unroll
        for (int w = 1; w < 8; w++) { Ut += sU[w]; Wt += sW[w]; }
        g_scal[(size_t)chunk * BB + b] = make_float2(Ut, Wt);
    }
}

// ============================================================================
// Pass B: out[b,m] = (sum_chunk partial[chunk,b,m] + W_b * k[b,m]) / U_b
// grid = 256 blocks x 256 threads. Block handles 64 m-columns of one batch;
// 4 thread-quarters each sum 8 chunks (coalesced: chunk-major layout).
// Partials are L2-resident (2 MB just written).
// ============================================================================
__global__ void k_passB(const float* __restrict__ k, float* __restrict__ out)
{
    const int b  = blockIdx.x >> 2;
    const int m0 = ((int)blockIdx.x & 3) * 64;
    const int t  = threadIdx.x;
    const int quarter = t >> 6;        // chunks [quarter*8, quarter*8+8)
    const int ml      = t & 63;

    float acc = 0.f;
    #pragma unroll
    for (int j = 0; j < 8; j++) {
        int chunk = quarter * 8 + j;
        acc += g_partial[((size_t)chunk * BB + b) * MM + m0 + ml];
    }

    __shared__ float red[4][64];
    __shared__ float sU, sW;
    red[quarter][ml] = acc;

    if (t < 32) {     // warp 0: reduce the 32 per-chunk scalars for batch b
        float2 sc = g_scal[(size_t)t * BB + b];
        float u = sc.x, w = sc.y;
        #pragma unroll
        for (int off = 16; off > 0; off >>= 1) {
            u += __shfl_down_sync(0xffffffffu, u, off);
            w += __shfl_down_sync(0xffffffffu, w, off);
        }
        if (t == 0) { sU = u; sW = w; }
    }
    __syncthreads();

    if (t < 64) {
        float tot = red[0][t] + red[1][t] + red[2][t] + red[3][t];
        float kvv = k[(size_t)b * MM + m0 + t];
        out[(size_t)b * MM + m0 + t] = (tot + sW * kvv) / sU;
    }
}

// ============================================================================
extern "C" void kernel_launch(void* const* d_in, const int* in_sizes, int n_in,
                              void* d_out, int out_size)
{
    const float* mem       = (const float*)d_in[0];   // (64,2048,256) f32
    const float* k         = (const float*)d_in[1];   // (64,256) f32
    const float* g         = (const float*)d_in[2];   // (64,1) f32
    // d_in[3] gamma: unused (dead w.r.t. output)
    const float* w_prev    = (const float*)d_in[4];   // (64,2,2048) f32
    const int*   w_lu_prev = (const int*)d_in[5];     // (64,2048) i32
    // d_in[6] n: unused (sort/w_lu are dead w.r.t. output)
    float* out = (float*)d_out;                       // (64,256) f32

    k_passA<<<BB * CHUNKS, 256>>>(mem, k, g, w_prev, w_lu_prev);
    k_passB<<<BB * 4, 256>>>(k, out);
}